// round 1
// baseline (speedup 1.0000x reference)
#include <cuda_runtime.h>
#include <cuda_bf16.h>

#define NU      50001
#define NI      100001
#define NN      150002
#define DD      64
#define NE      2000000
#define BATCHSZ 2048
#define EPSF    1e-9f
#define GAMMAF  1e-10f

// Scratch (static device arrays; no runtime allocation)
__device__ __align__(128) float g_total[(size_t)NN * DD];   // 38.4 MB
__device__ __align__(128) float g_acc[(size_t)NN * DD];     // 38.4 MB
__device__ float g_bpr[2 * BATCHSZ];
__device__ float g_sqp[1024];

// ---------------------------------------------------------------------------
// 1) total = concat(user_emb, item_emb); acc = 0
// ---------------------------------------------------------------------------
__global__ void init_kernel(const float4* __restrict__ ue, const float4* __restrict__ ie) {
    int i = blockIdx.x * blockDim.x + threadIdx.x;
    const int tot4 = NN * DD / 4;       // 2,400,032
    const int nu4  = NU * DD / 4;       //   800,016
    if (i < tot4) {
        float4 v = (i < nu4) ? ue[i] : ie[i - nu4];
        ((float4*)g_total)[i] = v;
        ((float4*)g_acc)[i]   = make_float4(0.f, 0.f, 0.f, 0.f);
    }
}

// ---------------------------------------------------------------------------
// 2) scatter: acc[dst] += norm[src] * total[src]   (16 threads / edge, float4)
// ---------------------------------------------------------------------------
__global__ __launch_bounds__(256) void scatter_kernel(
    const int* __restrict__ src, const int* __restrict__ dst,
    const float* __restrict__ oldd, const float* __restrict__ nowd,
    const float* __restrict__ dwp)
{
    int tid = blockIdx.x * blockDim.x + threadIdx.x;
    int e = tid >> 4;
    if (e >= NE) return;
    int p = tid & 15;

    int s = __ldg(src + e);
    int d = __ldg(dst + e);

    float dw  = __ldg(dwp);
    float den = sqrtf(fmaxf(__ldg(oldd + s) * dw, 0.f) + __ldg(nowd + s));
    float ns  = 1.f / (den + EPSF);

    float4 v = *(const float4*)(g_total + (size_t)s * DD + p * 4);
    float* o = g_acc + (size_t)d * DD + p * 4;

    // vector reduction (no return) — 1 L2 atomic slot for 16B instead of 4
    asm volatile("red.global.add.v4.f32 [%0], {%1, %2, %3, %4};"
                 :: "l"(o), "f"(ns * v.x), "f"(ns * v.y), "f"(ns * v.z), "f"(ns * v.w)
                 : "memory");
}

// ---------------------------------------------------------------------------
// 3) combine: e1 = norm*acc; mean of [total, c00*ls0*rs + c01*total,
//    c10*ls1*rs + c11*e1]; row-normalize; total += mean; acc = 0
//    (one warp per node, float2 per lane)
// ---------------------------------------------------------------------------
__global__ __launch_bounds__(256) void combine_kernel(
    const float* __restrict__ oldd, const float* __restrict__ nowd,
    const float* __restrict__ ls,      // last_stage[b] : [2][NN][DD]
    const float* __restrict__ dwp, const float* __restrict__ owp,
    const float* __restrict__ cw)      // conv_w[b] : 4 floats
{
    int node = blockIdx.x * (blockDim.x >> 5) + (threadIdx.x >> 5);
    if (node >= NN) return;
    int lane = threadIdx.x & 31;

    float dw = __ldg(dwp), ow = __ldg(owp);
    float c00 = __ldg(cw + 0), c01 = __ldg(cw + 1);
    float c10 = __ldg(cw + 2), c11 = __ldg(cw + 3);

    float od = __ldg(oldd + node), nd = __ldg(nowd + node);
    float den = sqrtf(fmaxf(od * dw, 0.f) + nd);
    float inv = 1.f / (den + EPSF);
    float rs  = sqrtf(fmaxf(od * ow, 0.f)) * inv;   // old_scale / (den + eps)

    size_t base = (size_t)node * DD + lane * 2;
    float2 t  = *(const float2*)(g_total + base);
    float2 a  = *(const float2*)(g_acc   + base);
    float2 l0 = *(const float2*)(ls + base);
    float2 l1 = *(const float2*)(ls + (size_t)NN * DD + base);

    float e1x = inv * a.x, e1y = inv * a.y;
    float mx = (t.x + (c00 * l0.x * rs + c01 * t.x) + (c10 * l1.x * rs + c11 * e1x)) * (1.f / 3.f);
    float my = (t.y + (c00 * l0.y * rs + c01 * t.y) + (c10 * l1.y * rs + c11 * e1y)) * (1.f / 3.f);

    float sq = mx * mx + my * my;
    #pragma unroll
    for (int o = 16; o; o >>= 1) sq += __shfl_xor_sync(0xffffffffu, sq, o);
    float rn = 1.f / fmaxf(sqrtf(sq), 1e-12f);

    t.x += mx * rn;
    t.y += my * rn;
    *(float2*)(g_total + base) = t;
    *(float2*)(g_acc + base)   = make_float2(0.f, 0.f);   // ready for next behavior
}

// ---------------------------------------------------------------------------
// 4) BPR loss per behavior (one warp per sample)
// ---------------------------------------------------------------------------
__global__ __launch_bounds__(256) void loss_kernel(const int* __restrict__ bdata, int b) {
    int w = (blockIdx.x * blockDim.x + threadIdx.x) >> 5;
    if (w >= BATCHSZ) return;
    int lane = threadIdx.x & 31;

    const int* r = bdata + (size_t)w * 6 + (size_t)b * 3;  // (BATCH, 2, 3)
    int u  = __ldg(r + 0);
    int pi = NU + __ldg(r + 1);
    int ni = NU + __ldg(r + 2);

    float2 uv = *(const float2*)(g_total + (size_t)u  * DD + lane * 2);
    float2 pv = *(const float2*)(g_total + (size_t)pi * DD + lane * 2);
    float2 nv = *(const float2*)(g_total + (size_t)ni * DD + lane * 2);

    float s0 = uv.x * pv.x + uv.y * pv.y;
    float s1 = uv.x * nv.x + uv.y * nv.y;
    #pragma unroll
    for (int o = 16; o; o >>= 1) {
        s0 += __shfl_xor_sync(0xffffffffu, s0, o);
        s1 += __shfl_xor_sync(0xffffffffu, s1, o);
    }
    if (lane == 0) {
        float diff = s0 - s1;
        float sig  = 1.f / (1.f + expf(-diff));
        g_bpr[b * BATCHSZ + w] = -logf(GAMMAF + sig);
    }
}

// ---------------------------------------------------------------------------
// 5) sum of squares for reg term: blocks [0,512) user, [512,1024) item
// ---------------------------------------------------------------------------
__global__ __launch_bounds__(256) void sumsq_kernel(const float* __restrict__ ue,
                                                    const float* __restrict__ ie) {
    __shared__ float sh[256];
    int which = blockIdx.x >> 9;
    int blk   = blockIdx.x & 511;
    const float* p = which ? ie : ue;
    int n = which ? NI * DD : NU * DD;

    float acc = 0.f;
    for (int i = blk * 256 + threadIdx.x; i < n; i += 512 * 256) {
        float v = p[i];
        acc += v * v;
    }
    sh[threadIdx.x] = acc;
    __syncthreads();
    for (int s = 128; s; s >>= 1) {
        if (threadIdx.x < s) sh[threadIdx.x] += sh[threadIdx.x + s];
        __syncthreads();
    }
    if (threadIdx.x == 0) g_sqp[blockIdx.x] = sh[0];
}

// ---------------------------------------------------------------------------
// 6) final deterministic reduction -> out[0]
// ---------------------------------------------------------------------------
__global__ void final_kernel(float* __restrict__ out) {
    __shared__ float sh[256];
    int t = threadIdx.x;

    float a = 0.f;
    for (int i = t; i < 2 * BATCHSZ; i += 256) a += g_bpr[i];
    float su = 0.f, si = 0.f;
    for (int i = t; i < 512; i += 256)  su += g_sqp[i];
    for (int i = 512 + t; i < 1024; i += 256) si += g_sqp[i];

    // fixed-order shared reductions
    float res[3] = {a, su, si};
    float red[3];
    #pragma unroll
    for (int k = 0; k < 3; k++) {
        sh[t] = res[k];
        __syncthreads();
        for (int s = 128; s; s >>= 1) {
            if (t < s) sh[t] += sh[t + s];
            __syncthreads();
        }
        red[k] = sh[0];
        __syncthreads();
    }

    if (t == 0) {
        float total_loss = red[0] * (1.f / BATCHSZ);                 // sum of both means
        float emb_loss   = (sqrtf(red[1]) + sqrtf(red[2])) / (float)NI;
        out[0] = total_loss + 1e-4f * emb_loss;
    }
}

// ---------------------------------------------------------------------------
extern "C" void kernel_launch(void* const* d_in, const int* in_sizes, int n_in,
                              void* d_out, int out_size) {
    const float* ue    = (const float*)d_in[0];
    const float* ie    = (const float*)d_in[1];
    const float* nowd  = (const float*)d_in[2];
    const float* oldd  = (const float*)d_in[3];
    const float* ls    = (const float*)d_in[4];
    const float* dw    = (const float*)d_in[5];
    const float* ow    = (const float*)d_in[6];
    const float* cw    = (const float*)d_in[7];
    const int*   src   = (const int*)d_in[8];
    const int*   dst   = (const int*)d_in[9];
    const int*   bdata = (const int*)d_in[10];
    float*       out   = (float*)d_out;

    init_kernel<<<(NN * DD / 4 + 255) / 256, 256>>>((const float4*)ue, (const float4*)ie);

    for (int b = 0; b < 2; b++) {
        scatter_kernel<<<(NE * 16 + 255) / 256, 256>>>(
            src + (size_t)b * NE, dst + (size_t)b * NE,
            oldd + (size_t)b * NN, nowd + (size_t)b * NN, dw);
        combine_kernel<<<(NN + 7) / 8, 256>>>(
            oldd + (size_t)b * NN, nowd + (size_t)b * NN,
            ls + (size_t)b * 2 * NN * DD, dw, ow, cw + b * 4);
        loss_kernel<<<(BATCHSZ * 32 + 255) / 256, 256>>>(bdata, b);
    }

    sumsq_kernel<<<1024, 256>>>(ue, ie);
    final_kernel<<<1, 256>>>(out);
}